// round 3
// baseline (speedup 1.0000x reference)
#include <cuda_runtime.h>
#include <cuda_bf16.h>

#define TX 64
#define TY 32
#define NT 256

// Cross-block loss accumulator.
__device__ double g_acc;

__global__ void zero_acc_kernel() { g_acc = 0.0; }

__global__ void finalize_kernel(float* out) {
    out[0] = (float)(g_acc / (256.0 * 254.0 * 254.0));
}

__global__ __launch_bounds__(NT) void pde_loss_kernel(
    const float* __restrict__ pred,   // [256,256,256]
    const float* __restrict__ rhs,    // [256,254,254]
    const float* __restrict__ kL,     // [256,3,3]
    const float* __restrict__ kD,     // [256,3,3]
    const float* __restrict__ RR,     // [256,256,256] (broadcast meshgrid)
    const float* __restrict__ ZZ,     // [256,256,256]
    const float* __restrict__ G)      // [3,3]
{
    const int H = 256, W = 256, OH = 254, OW = 254;
    const int b   = blockIdx.z;
    const int tx0 = blockIdx.x * TX;
    const int ty0 = blockIdx.y * TY;

    // pred tile: rows ty0-1..ty0+34 (36), cols tx0-1..tx0+66 (68), stride 72 (16B-mult)
    __shared__ __align__(16) float sp[36][72];
    // GS tile: rows ty0-1..ty0+32 (34), cols tx0-1..tx0+64 (66 valid), stride 68 (16B-mult)
    __shared__ __align__(16) float sg[34][68];
    __shared__ float rinv_s[68];
    __shared__ float wpart[NT / 32];

    const int tid = threadIdx.x;
    const size_t bHW = (size_t)b * H * W;

    // Per-block-uniform coefficients live in registers (broadcast LDG, L1-resident).
    float cL[9], cD[9], cG[9];
    #pragma unroll
    for (int i = 0; i < 9; i++) {
        cL[i] = kL[b * 9 + i];
        cD[i] = kD[b * 9 + i];
        cG[i] = G[i];
    }

    float hr = RR[bHW + W + 2]     - RR[bHW + W + 1];
    float hz = ZZ[bHW + 2 * W + 1] - ZZ[bHW + W + 1];
    float hr2 = hr * hr, hz2 = hz * hz;
    float scale = (-2.0f * (hr2 + hz2)) / (hr2 * hz2);

    if (tid < 68) {
        int q = tx0 - 1 + tid;  // GS column
        float r = (q >= 0 && q < OW) ? RR[bHW + W + (q + 1)] : 1.0f;
        rinv_s[tid] = 1.0f / r;
    }

    // Load pred tile starting at (ty0-1, tx0-1); zero-fill out of range, pad cols 68..71.
    const float* pb = pred + bHW;
    for (int idx = tid; idx < 36 * 72; idx += NT) {
        int sy = idx / 72, sx = idx % 72;
        int gy = ty0 - 1 + sy, gx = tx0 - 1 + sx;
        float v = 0.0f;
        if (sx < 68 && gy >= 0 && gy < H && gx >= 0 && gx < W) v = pb[gy * W + gx];
        sp[sy][sx] = v;
    }
    __syncthreads();

    // ---- Stage 1: GS tile, 4 outputs/thread via float4 smem loads ----
    // GS point (p,q) = pred[p..p+2][q..q+2]; sp[syl+u][sx+j+v] = pred[p+u][q+v].
    for (int c = tid; c < 34 * 17; c += NT) {
        int syl = c / 17;
        int sx  = (c % 17) * 4;
        int p   = ty0 - 1 + syl;
        float sl[4] = {0, 0, 0, 0}, sd[4] = {0, 0, 0, 0};
        #pragma unroll
        for (int u = 0; u < 3; u++) {
            float4 a  = *(const float4*)&sp[syl + u][sx];
            float4 bb = *(const float4*)&sp[syl + u][sx + 4];
            float rr[6] = {a.x, a.y, a.z, a.w, bb.x, bb.y};
            #pragma unroll
            for (int v = 0; v < 3; v++) {
                float l = cL[3 * u + v], d = cD[3 * u + v];
                #pragma unroll
                for (int j = 0; j < 4; j++) {
                    sl[j] = fmaf(rr[j + v], l, sl[j]);
                    sd[j] = fmaf(rr[j + v], d, sd[j]);
                }
            }
        }
        bool prow = (p >= 0 && p < OH);
        float g4[4];
        #pragma unroll
        for (int j = 0; j < 4; j++) {
            int q = tx0 - 1 + sx + j;
            float g = scale * fmaf(sd[j], rinv_s[sx + j], sl[j]);
            g4[j] = (prow && q >= 0 && q < OW && (sx + j) < 66) ? g : 0.0f;
        }
        float4 gout = make_float4(g4[0], g4[1], g4[2], g4[3]);
        *(float4*)&sg[syl][sx] = gout;
    }
    __syncthreads();

    // ---- Stage 2: Gaussian smooth + MSE accumulate, 4 outputs/thread ----
    float acc = 0.0f;
    const float* rb = rhs + (size_t)b * OH * OW;
    for (int c = tid; c < 32 * 16; c += NT) {
        int oyl = c / 16;
        int ox4 = (c % 16) * 4;
        int oy  = ty0 + oyl;
        float s[4] = {0, 0, 0, 0};
        #pragma unroll
        for (int dy = 0; dy < 3; dy++) {
            float4 a  = *(const float4*)&sg[oyl + dy][ox4];
            float4 bb = *(const float4*)&sg[oyl + dy][ox4 + 4];
            float rr[6] = {a.x, a.y, a.z, a.w, bb.x, bb.y};
            #pragma unroll
            for (int dx = 0; dx < 3; dx++) {
                float gv = cG[3 * dy + dx];
                #pragma unroll
                for (int j = 0; j < 4; j++) s[j] = fmaf(rr[j + dx], gv, s[j]);
            }
        }
        int ox = tx0 + ox4;
        if (oy < OH) {
            if (ox + 3 < OW) {
                float2 r01 = *(const float2*)&rb[oy * OW + ox];
                float2 r23 = *(const float2*)&rb[oy * OW + ox + 2];
                float d0 = s[0] - r01.x, d1 = s[1] - r01.y;
                float d2 = s[2] - r23.x, d3 = s[3] - r23.y;
                acc = fmaf(d0, d0, acc);
                acc = fmaf(d1, d1, acc);
                acc = fmaf(d2, d2, acc);
                acc = fmaf(d3, d3, acc);
            } else {
                #pragma unroll
                for (int j = 0; j < 4; j++) {
                    if (ox + j < OW) {
                        float d = s[j] - rb[oy * OW + ox + j];
                        acc = fmaf(d, d, acc);
                    }
                }
            }
        }
    }

    // Block reduce + one double atomic per block.
    #pragma unroll
    for (int off = 16; off > 0; off >>= 1)
        acc += __shfl_xor_sync(0xFFFFFFFFu, acc, off);
    if ((tid & 31) == 0) wpart[tid >> 5] = acc;
    __syncthreads();
    if (tid == 0) {
        double s = 0.0;
        #pragma unroll
        for (int w = 0; w < NT / 32; w++) s += (double)wpart[w];
        atomicAdd(&g_acc, s);
    }
}

extern "C" void kernel_launch(void* const* d_in, const int* in_sizes, int n_in,
                              void* d_out, int out_size) {
    const float* pred = (const float*)d_in[0];
    const float* rhs  = (const float*)d_in[1];
    const float* kL   = (const float*)d_in[2];
    const float* kD   = (const float*)d_in[3];
    const float* RR   = (const float*)d_in[4];
    const float* ZZ   = (const float*)d_in[5];
    const float* G    = (const float*)d_in[6];
    float* out = (float*)d_out;

    zero_acc_kernel<<<1, 1>>>();
    dim3 grid((254 + TX - 1) / TX, (254 + TY - 1) / TY, 256);  // 4 x 8 x 256
    pde_loss_kernel<<<grid, NT>>>(pred, rhs, kL, kD, RR, ZZ, G);
    finalize_kernel<<<1, 1>>>(out);
}

// round 4
// speedup vs baseline: 1.2524x; 1.2524x over previous
#include <cuda_runtime.h>
#include <cuda_bf16.h>

#define TX 32
#define TY 32
#define NT 256
#define NBLK (8 * 8 * 256)

__device__ float    g_part[NBLK];
__device__ unsigned g_cnt;  // zero-initialized; last block resets it each call

template <bool INTERIOR>
__device__ __forceinline__ float tile_compute(
    const float* __restrict__ pred, const float* __restrict__ rhs,
    const float* __restrict__ kL, const float* __restrict__ kD,
    const float* __restrict__ RR, const float* __restrict__ ZZ,
    const float* __restrict__ G,
    int b, int tx0, int ty0, int tid,
    float (*sp)[37], float (*sg)[35], float* rinv_s)
{
    const int H = 256, W = 256, OH = 254, OW = 254;
    const size_t bHW = (size_t)b * H * W;
    const float* pb = pred + bHW;

    // Grid-spacing scale (RR/ZZ are broadcast meshgrids; 4 scalar reads).
    float hr = RR[bHW + W + 2]     - RR[bHW + W + 1];
    float hz = ZZ[bHW + 2 * W + 1] - ZZ[bHW + W + 1];
    float hr2 = hr * hr, hz2 = hz * hz;
    float scale = (-2.0f * (hr2 + hz2)) / (hr2 * hz2);

    // Coefficients in registers, Laplace/Df_dr pre-scaled by `scale`.
    float cL[9], cD[9];
    #pragma unroll
    for (int i = 0; i < 9; i++) {
        cL[i] = scale * kL[b * 9 + i];
        cD[i] = scale * kD[b * 9 + i];
    }

    if (tid < 34) {
        int q = tx0 - 1 + tid;  // GS column index
        float r = (INTERIOR || (q >= 0 && q < OW)) ? RR[bHW + W + (q + 1)] : 1.0f;
        rinv_s[tid] = 1.0f / r;
    }

    // Load pred tile: rows ty0-1..ty0+34 (36), cols tx0-1..tx0+34 (36).
    #pragma unroll
    for (int it = 0; it < 6; it++) {
        int idx = tid + it * NT;
        if (idx < 36 * 36) {
            int sy = idx / 36, sx = idx % 36;
            int gy = ty0 - 1 + sy, gx = tx0 - 1 + sx;
            float v;
            if (INTERIOR) {
                v = pb[gy * W + gx];
            } else {
                v = (gy >= 0 && gy < H && gx >= 0 && gx < W) ? pb[gy * W + gx] : 0.0f;
            }
            sp[sy][sx] = v;
        }
    }
    __syncthreads();

    // Stage 1: GS on 34x34 halo tile (rows/cols ty0-1.., tx0-1..).
    #pragma unroll
    for (int it = 0; it < 5; it++) {
        int idx = tid + it * NT;
        if (idx < 34 * 34) {
            int syl = idx / 34, sx = idx % 34;
            float sl = 0.0f, sd = 0.0f;
            #pragma unroll
            for (int u = 0; u < 3; u++) {
                #pragma unroll
                for (int v = 0; v < 3; v++) {
                    float x = sp[syl + u][sx + v];
                    sl = fmaf(x, cL[3 * u + v], sl);
                    sd = fmaf(x, cD[3 * u + v], sd);
                }
            }
            float g = fmaf(sd, rinv_s[sx], sl);  // scale already folded in
            if (!INTERIOR) {
                int p = ty0 - 1 + syl, q = tx0 - 1 + sx;
                if (p < 0 || p >= OH || q < 0 || q >= OW) g = 0.0f;
            }
            sg[syl][sx] = g;
        }
    }
    __syncthreads();

    // Stage 2: Gaussian smooth (SAME) + squared error vs rhs.
    float cG[9];
    #pragma unroll
    for (int i = 0; i < 9; i++) cG[i] = G[i];

    float acc = 0.0f;
    const float* rb = rhs + (size_t)b * OH * OW;
    #pragma unroll
    for (int it = 0; it < 4; it++) {
        int idx = tid + it * NT;
        int oyl = idx >> 5, oxl = idx & 31;
        int oy = ty0 + oyl, ox = tx0 + oxl;
        if (INTERIOR || (oy < OH && ox < OW)) {
            float s = 0.0f;
            #pragma unroll
            for (int dy = 0; dy < 3; dy++) {
                #pragma unroll
                for (int dx = 0; dx < 3; dx++) {
                    s = fmaf(sg[oyl + dy][oxl + dx], cG[3 * dy + dx], s);
                }
            }
            float d = s - rb[oy * OW + ox];
            acc = fmaf(d, d, acc);
        }
    }
    return acc;
}

__global__ __launch_bounds__(NT) void pde_loss_kernel(
    const float* __restrict__ pred, const float* __restrict__ rhs,
    const float* __restrict__ kL, const float* __restrict__ kD,
    const float* __restrict__ RR, const float* __restrict__ ZZ,
    const float* __restrict__ G, float* __restrict__ out)
{
    __shared__ float sp[36][37];
    __shared__ float sg[34][35];
    __shared__ float rinv_s[34];
    __shared__ float wpart[NT / 32];
    __shared__ unsigned is_last_s;

    const int tid = threadIdx.x;
    const int b   = blockIdx.z;
    const int tx0 = blockIdx.x * TX;
    const int ty0 = blockIdx.y * TY;
    const bool interior = (blockIdx.x >= 1 && blockIdx.x <= 6 &&
                           blockIdx.y >= 1 && blockIdx.y <= 6);

    float acc;
    if (interior)
        acc = tile_compute<true >(pred, rhs, kL, kD, RR, ZZ, G, b, tx0, ty0, tid, sp, sg, rinv_s);
    else
        acc = tile_compute<false>(pred, rhs, kL, kD, RR, ZZ, G, b, tx0, ty0, tid, sp, sg, rinv_s);

    // Block reduce.
    #pragma unroll
    for (int off = 16; off > 0; off >>= 1)
        acc += __shfl_xor_sync(0xFFFFFFFFu, acc, off);
    if ((tid & 31) == 0) wpart[tid >> 5] = acc;
    __syncthreads();

    const int bid = (blockIdx.z * gridDim.y + blockIdx.y) * gridDim.x + blockIdx.x;
    if (tid == 0) {
        float s = 0.0f;
        #pragma unroll
        for (int w = 0; w < NT / 32; w++) s += wpart[w];
        __stcg(&g_part[bid], s);
        __threadfence();
        unsigned old = atomicAdd(&g_cnt, 1u);
        is_last_s = (old == NBLK - 1) ? 1u : 0u;
    }
    __syncthreads();

    // Last block reduces all partials and writes the final mean.
    if (is_last_s) {
        double dsum = 0.0;
        const float4* p4 = (const float4*)g_part;
        #pragma unroll
        for (int it = 0; it < NBLK / 4 / NT; it++) {
            float4 v = __ldcg(&p4[tid + it * NT]);
            dsum += (double)v.x + (double)v.y + (double)v.z + (double)v.w;
        }
        #pragma unroll
        for (int off = 16; off > 0; off >>= 1)
            dsum += __shfl_xor_sync(0xFFFFFFFFu, dsum, off);
        __shared__ double dpart[NT / 32];
        if ((tid & 31) == 0) dpart[tid >> 5] = dsum;
        __syncthreads();
        if (tid == 0) {
            double t = 0.0;
            #pragma unroll
            for (int w = 0; w < NT / 32; w++) t += dpart[w];
            out[0] = (float)(t / (256.0 * 254.0 * 254.0));
            g_cnt = 0;  // reset for next (graph-replayed) call
        }
    }
}

extern "C" void kernel_launch(void* const* d_in, const int* in_sizes, int n_in,
                              void* d_out, int out_size) {
    const float* pred = (const float*)d_in[0];
    const float* rhs  = (const float*)d_in[1];
    const float* kL   = (const float*)d_in[2];
    const float* kD   = (const float*)d_in[3];
    const float* RR   = (const float*)d_in[4];
    const float* ZZ   = (const float*)d_in[5];
    const float* G    = (const float*)d_in[6];
    float* out = (float*)d_out;

    dim3 grid(8, 8, 256);
    pde_loss_kernel<<<grid, NT>>>(pred, rhs, kL, kD, RR, ZZ, G, out);
}

// round 5
// speedup vs baseline: 2.2164x; 1.7697x over previous
#include <cuda_runtime.h>
#include <cuda_bf16.h>

#define NT 256
#define WPB 8                       // warps per block
#define GROUPS 9                    // column groups, 30 output cols each (270 >= 254)
#define STRIPS 4                    // row strips: [0,63],[64,127],[128,191],[192,253]
#define NTASK (GROUPS * STRIPS * 256)        // 9216 warp tasks
#define NBLK (NTASK / WPB)                   // 1152 blocks

__device__ float    g_part[NBLK];
__device__ unsigned g_cnt;   // zero-init; last block resets each call

__global__ __launch_bounds__(NT, 4) void pde_loss_kernel(
    const float* __restrict__ pred,   // [256,256,256]
    const float* __restrict__ rhs,    // [256,254,254]
    const float* __restrict__ kL,     // [256,3,3]
    const float* __restrict__ kD,     // [256,3,3]
    const float* __restrict__ RR,     // [256,256,256] broadcast meshgrid
    const float* __restrict__ ZZ,     // [256,256,256]
    const float* __restrict__ G,      // [3,3] (separable [1,2,1]x[1,2,1]/16)
    float* __restrict__ out)
{
    const int tid  = threadIdx.x;
    const int lane = tid & 31;
    const int wid  = tid >> 5;

    const int task = blockIdx.x * WPB + wid;       // 0..9215
    const int b    = task / 36;                    // 36 = GROUPS*STRIPS
    const int rem  = task - b * 36;
    const int s    = rem / GROUPS;
    const int g    = rem - s * GROUPS;

    const int  q  = 30 * g - 1 + lane;             // GS column this lane computes
    const bool qv = (q >= 0 && q <= 253);
    const bool outv = qv && (lane >= 1) && (lane <= 30);
    const int  Y0 = s * 64;
    const int  Y1 = (s == STRIPS - 1) ? 253 : (Y0 + 63);

    const size_t bHW = (size_t)b * 65536;
    const float* pb = pred + bHW;
    const float* rb = rhs + (size_t)b * (254 * 254);

    // Grid-spacing scale; fold the Gaussian's 1/16 in too.
    float hr = RR[bHW + 256 + 2]     - RR[bHW + 256 + 1];
    float hz = ZZ[bHW + 2 * 256 + 1] - ZZ[bHW + 256 + 1];
    float hr2 = hr * hr, hz2 = hz * hz;
    float scale = ((-2.0f * (hr2 + hz2)) / (hr2 * hz2)) * 0.0625f;

    float cL[9], cD[9];
    #pragma unroll
    for (int i = 0; i < 9; i++) {
        cL[i] = scale * kL[b * 9 + i];
        cD[i] = scale * kD[b * 9 + i];
    }

    float rinv = 0.0f;
    if (qv) rinv = 1.0f / RR[bHW + 256 + (q + 1)];

    // Sliding 3x3 pred window (rows p..p+2, cols q..q+2). Preload rows Y0-1, Y0.
    float w00 = 0, w01 = 0, w02 = 0, w10 = 0, w11 = 0, w12 = 0;
    if (qv) {
        int r = Y0 - 1;
        if (r >= 0) {
            w00 = pb[r * 256 + q]; w01 = pb[r * 256 + q + 1]; w02 = pb[r * 256 + q + 2];
        }
        r = Y0;
        w10 = pb[r * 256 + q]; w11 = pb[r * 256 + q + 1]; w12 = pb[r * 256 + q + 2];
    }

    float h0 = 0.0f, h1 = 0.0f;   // Hs[p-2], Hs[p-1]
    float acc = 0.0f;

    #pragma unroll 3
    for (int p = Y0 - 1; p <= Y1 + 1; p++) {
        // Load pred row p+2 (window bottom).
        float w20 = 0, w21 = 0, w22 = 0;
        if (qv && p <= 253) {
            const float* pr = pb + (p + 2) * 256 + q;
            w20 = pr[0]; w21 = pr[1]; w22 = pr[2];
        }

        // GS[p][q] = scale/16 * (Lpsi + Dpsi_raw * rinv); zero outside [0,254).
        float sl, sd;
        sl = w00 * cL[0];            sd = w00 * cD[0];
        sl = fmaf(w01, cL[1], sl);   sd = fmaf(w01, cD[1], sd);
        sl = fmaf(w02, cL[2], sl);   sd = fmaf(w02, cD[2], sd);
        sl = fmaf(w10, cL[3], sl);   sd = fmaf(w10, cD[3], sd);
        sl = fmaf(w11, cL[4], sl);   sd = fmaf(w11, cD[4], sd);
        sl = fmaf(w12, cL[5], sl);   sd = fmaf(w12, cD[5], sd);
        sl = fmaf(w20, cL[6], sl);   sd = fmaf(w20, cD[6], sd);
        sl = fmaf(w21, cL[7], sl);   sd = fmaf(w21, cD[7], sd);
        sl = fmaf(w22, cL[8], sl);   sd = fmaf(w22, cD[8], sd);
        float gs = (p >= 0 && p <= 253) ? fmaf(sd, rinv, sl) : 0.0f;

        // Horizontal [1,2,1] via shuffles (valid on lanes 1..30).
        float up = __shfl_up_sync(0xFFFFFFFFu, gs, 1);
        float dn = __shfl_down_sync(0xFFFFFFFFu, gs, 1);
        float hs = up + fmaf(2.0f, gs, dn);

        // Vertical [1,2,1]: emit output row oy = p-1 once 3 Hs rows known.
        if (p >= Y0 + 1 && outv) {
            int oy = p - 1;
            float sm = h0 + fmaf(2.0f, h1, hs);
            float d = sm - rb[oy * 254 + q];
            acc = fmaf(d, d, acc);
        }

        h0 = h1; h1 = hs;
        w00 = w10; w01 = w11; w02 = w12;
        w10 = w20; w11 = w21; w12 = w22;
    }

    // ---- block reduction, then last-block global reduction ----
    __shared__ float wpart[WPB];
    __shared__ unsigned is_last_s;

    #pragma unroll
    for (int off = 16; off > 0; off >>= 1)
        acc += __shfl_xor_sync(0xFFFFFFFFu, acc, off);
    if (lane == 0) wpart[wid] = acc;
    __syncthreads();

    if (tid == 0) {
        float ssum = 0.0f;
        #pragma unroll
        for (int w = 0; w < WPB; w++) ssum += wpart[w];
        __stcg(&g_part[blockIdx.x], ssum);
        __threadfence();
        unsigned old = atomicAdd(&g_cnt, 1u);
        is_last_s = (old == NBLK - 1) ? 1u : 0u;
    }
    __syncthreads();

    if (is_last_s) {
        double dsum = 0.0;
        const float4* p4 = (const float4*)g_part;
        for (int i = tid; i < NBLK / 4; i += NT) {
            float4 v = __ldcg(&p4[i]);
            dsum += (double)v.x + (double)v.y + (double)v.z + (double)v.w;
        }
        #pragma unroll
        for (int off = 16; off > 0; off >>= 1)
            dsum += __shfl_xor_sync(0xFFFFFFFFu, dsum, off);
        __shared__ double dpart[NT / 32];
        if (lane == 0) dpart[wid] = dsum;
        __syncthreads();
        if (tid == 0) {
            double t = 0.0;
            #pragma unroll
            for (int w = 0; w < NT / 32; w++) t += dpart[w];
            out[0] = (float)(t / (256.0 * 254.0 * 254.0));
            g_cnt = 0;  // reset for next graph replay
        }
    }
}

extern "C" void kernel_launch(void* const* d_in, const int* in_sizes, int n_in,
                              void* d_out, int out_size) {
    const float* pred = (const float*)d_in[0];
    const float* rhs  = (const float*)d_in[1];
    const float* kL   = (const float*)d_in[2];
    const float* kD   = (const float*)d_in[3];
    const float* RR   = (const float*)d_in[4];
    const float* ZZ   = (const float*)d_in[5];
    const float* G    = (const float*)d_in[6];
    float* out = (float*)d_out;

    pde_loss_kernel<<<NBLK, NT>>>(pred, rhs, kL, kD, RR, ZZ, G, out);
}

// round 7
// speedup vs baseline: 2.4221x; 1.0928x over previous
#include <cuda_runtime.h>
#include <cuda_bf16.h>

#define NT 256
#define WPB 8                        // warps per block
#define GROUPS 9                     // column groups, 30 output cols each
#define STRIPS 8                     // 32-row strips (last is 30)
#define NTASK (GROUPS * STRIPS * 256)          // 18432 warp tasks
#define NBLK (NTASK / WPB)                     // 2304 blocks

__device__ float    g_part[NBLK];
__device__ unsigned g_cnt;   // zero-init; last block resets each call

__global__ __launch_bounds__(NT) void pde_loss_kernel(
    const float* __restrict__ pred,   // [256,256,256]
    const float* __restrict__ rhs,    // [256,254,254]
    const float* __restrict__ kL,     // [256,3,3]
    const float* __restrict__ kD,     // [256,3,3]
    const float* __restrict__ RR,     // [256,256,256] broadcast meshgrid
    const float* __restrict__ ZZ,     // [256,256,256]
    const float* __restrict__ G,      // [3,3] separable [1,2,1]^2/16
    float* __restrict__ out)
{
    const int tid  = threadIdx.x;
    const int lane = tid & 31;
    const int wid  = tid >> 5;

    const int task = blockIdx.x * WPB + wid;           // 0..NTASK-1
    const int b    = task / (GROUPS * STRIPS);
    const int rem  = task - b * (GROUPS * STRIPS);
    const int s    = rem / GROUPS;
    const int g    = rem - s * GROUPS;

    const int  q    = 30 * g - 1 + lane;               // GS column for this lane
    const bool qv   = (q >= 0 && q <= 253);
    const bool outv = qv && (lane >= 1) && (lane <= 30);
    const int  Y0 = s * 32;
    const int  Y1 = (Y0 + 31 > 253) ? 253 : (Y0 + 31);

    const size_t bHW = (size_t)b * 65536;
    const float* pb = pred + bHW;
    const float* rb = rhs + (size_t)b * (254 * 254);

    // scale * 1/16 (Gaussian folded); then fold rinv into one 3x3 stencil.
    float hr = RR[bHW + 256 + 2]     - RR[bHW + 256 + 1];
    float hz = ZZ[bHW + 2 * 256 + 1] - ZZ[bHW + 256 + 1];
    float hr2 = hr * hr, hz2 = hz * hz;
    float scale = ((-2.0f * (hr2 + hz2)) / (hr2 * hz2)) * 0.0625f;

    float rinv = 0.0f;
    if (qv) rinv = 1.0f / RR[bHW + 256 + (q + 1)];

    // cE[uv] = scale * (kL[uv] + rinv * kD[uv])  -> GS = sum pred*cE  (9 FMA/row)
    float cE[9];
    #pragma unroll
    for (int i = 0; i < 9; i++)
        cE[i] = scale * fmaf(rinv, kD[b * 9 + i], kL[b * 9 + i]);

    // Sliding 3x3 window rows p..p+2, cols q..q+2, plus 1-row prefetch.
    float w00 = 0, w01 = 0, w02 = 0, w10 = 0, w11 = 0, w12 = 0;
    float pf0 = 0, pf1 = 0, pf2 = 0;
    if (qv) {
        if (Y0 - 1 >= 0) {
            const float* pr = pb + (Y0 - 1) * 256 + q;
            w00 = pr[0]; w01 = pr[1]; w02 = pr[2];
        }
        {
            const float* pr = pb + Y0 * 256 + q;
            w10 = pr[0]; w11 = pr[1]; w12 = pr[2];
        }
        {
            const float* pr = pb + (Y0 + 1) * 256 + q;  // row (Y0-1)+2
            pf0 = pr[0]; pf1 = pr[1]; pf2 = pr[2];
        }
    }

    float h0 = 0.0f, h1 = 0.0f;
    float acc = 0.0f;

    #pragma unroll 4
    for (int p = Y0 - 1; p <= Y1 + 1; p++) {
        // Consume prefetched bottom row (row p+2), prefetch row p+3.
        float w20 = pf0, w21 = pf1, w22 = pf2;
        bool pfv = qv && (p + 3 <= 255);
        const float* pr = pb + (p + 3) * 256 + q;
        pf0 = pfv ? pr[0] : 0.0f;
        pf1 = pfv ? pr[1] : 0.0f;
        pf2 = pfv ? pr[2] : 0.0f;

        // GS[p][q] via single folded stencil (scale & rinv pre-applied).
        float sl;
        sl = w00 * cE[0];
        sl = fmaf(w01, cE[1], sl);
        sl = fmaf(w02, cE[2], sl);
        sl = fmaf(w10, cE[3], sl);
        sl = fmaf(w11, cE[4], sl);
        sl = fmaf(w12, cE[5], sl);
        sl = fmaf(w20, cE[6], sl);
        sl = fmaf(w21, cE[7], sl);
        sl = fmaf(w22, cE[8], sl);
        float gs = (p >= 0 && p <= 253) ? sl : 0.0f;

        // Horizontal [1,2,1] via shuffles (valid on lanes 1..30).
        float up = __shfl_up_sync(0xFFFFFFFFu, gs, 1);
        float dn = __shfl_down_sync(0xFFFFFFFFu, gs, 1);
        float hs = up + fmaf(2.0f, gs, dn);

        // Vertical [1,2,1]: emit output row oy = p-1.
        if (p >= Y0 + 1 && outv) {
            int oy = p - 1;
            float sm = h0 + fmaf(2.0f, h1, hs);
            float d = sm - rb[oy * 254 + q];
            acc = fmaf(d, d, acc);
        }

        h0 = h1; h1 = hs;
        w00 = w10; w01 = w11; w02 = w12;
        w10 = w20; w11 = w21; w12 = w22;
    }

    // ---- block reduction, then last-block global reduction ----
    __shared__ float wpart[WPB];
    __shared__ unsigned is_last_s;

    #pragma unroll
    for (int off = 16; off > 0; off >>= 1)
        acc += __shfl_xor_sync(0xFFFFFFFFu, acc, off);
    if (lane == 0) wpart[wid] = acc;
    __syncthreads();

    if (tid == 0) {
        float ssum = 0.0f;
        #pragma unroll
        for (int w = 0; w < WPB; w++) ssum += wpart[w];
        __stcg(&g_part[blockIdx.x], ssum);
        __threadfence();
        unsigned old = atomicAdd(&g_cnt, 1u);
        is_last_s = (old == NBLK - 1) ? 1u : 0u;
    }
    __syncthreads();

    if (is_last_s) {
        double dsum = 0.0;
        const float4* p4 = (const float4*)g_part;
        for (int i = tid; i < NBLK / 4; i += NT) {
            float4 v = __ldcg(&p4[i]);
            dsum += (double)v.x + (double)v.y + (double)v.z + (double)v.w;
        }
        #pragma unroll
        for (int off = 16; off > 0; off >>= 1)
            dsum += __shfl_xor_sync(0xFFFFFFFFu, dsum, off);
        __shared__ double dpart[NT / 32];
        if (lane == 0) dpart[wid] = dsum;
        __syncthreads();
        if (tid == 0) {
            double t = 0.0;
            #pragma unroll
            for (int w = 0; w < NT / 32; w++) t += dpart[w];
            out[0] = (float)(t / (256.0 * 254.0 * 254.0));
            g_cnt = 0;  // reset for next graph replay
        }
    }
}

extern "C" void kernel_launch(void* const* d_in, const int* in_sizes, int n_in,
                              void* d_out, int out_size) {
    const float* pred = (const float*)d_in[0];
    const float* rhs  = (const float*)d_in[1];
    const float* kL   = (const float*)d_in[2];
    const float* kD   = (const float*)d_in[3];
    const float* RR   = (const float*)d_in[4];
    const float* ZZ   = (const float*)d_in[5];
    const float* G    = (const float*)d_in[6];
    float* out = (float*)d_out;

    pde_loss_kernel<<<NBLK, NT>>>(pred, rhs, kL, kD, RR, ZZ, G, out);
}